// round 2
// baseline (speedup 1.0000x reference)
#include <cuda_runtime.h>

// GlobalFeatureEncoder: 4x LSTM(H=256, in=1) + scalar embed + layernorm.
// B=8192 rows. Round 1: SIMT fp32 baseline with fma.rn.f32x2 packing.

#define TB 16          // batch rows per CTA
#define HU 256         // hidden units
#define NBATCH 8192
#define LN_EPS 1e-5f

// Scratch (allocation-free rule: __device__ globals)
// W2 layout: [l][k][h][4]  -> W2[((l*256+k)*256+h)*4 + j] = whh_l[(j*256+h)*256 + k]
__device__ float g_W2[4 * 256 * 256 * 4];
// wb layout: [l][h][8]: j<4 -> wih[j*256+h], j>=4 -> bih+bhh at same gate
__device__ float g_wb[4 * 256 * 8];

// ---------------- prep kernels ----------------

__global__ void prep_w2(const float* __restrict__ w0, const float* __restrict__ w1,
                        const float* __restrict__ w2, const float* __restrict__ w3) {
    int idx = blockIdx.x * 256 + threadIdx.x;      // 0 .. 4*256*256-1
    int l = idx >> 16;
    int k = (idx >> 8) & 255;
    int h = idx & 255;
    const float* w = (l == 0) ? w0 : (l == 1) ? w1 : (l == 2) ? w2 : w3;
    float4 v;
    v.x = w[(0 * 256 + h) * 256 + k];
    v.y = w[(1 * 256 + h) * 256 + k];
    v.z = w[(2 * 256 + h) * 256 + k];
    v.w = w[(3 * 256 + h) * 256 + k];
    reinterpret_cast<float4*>(g_W2)[idx] = v;
    (void)k;
}

__global__ void prep_wb(const float* __restrict__ wi0, const float* __restrict__ bi0, const float* __restrict__ bh0,
                        const float* __restrict__ wi1, const float* __restrict__ bi1, const float* __restrict__ bh1,
                        const float* __restrict__ wi2, const float* __restrict__ bi2, const float* __restrict__ bh2,
                        const float* __restrict__ wi3, const float* __restrict__ bi3, const float* __restrict__ bh3) {
    int idx = blockIdx.x * 256 + threadIdx.x;      // 0..1023
    int l = idx >> 8;
    int h = idx & 255;
    const float* wi = (l == 0) ? wi0 : (l == 1) ? wi1 : (l == 2) ? wi2 : wi3;
    const float* bi = (l == 0) ? bi0 : (l == 1) ? bi1 : (l == 2) ? bi2 : bi3;
    const float* bh = (l == 0) ? bh0 : (l == 1) ? bh1 : (l == 2) ? bh2 : bh3;
    float* dst = g_wb + idx * 8;
#pragma unroll
    for (int j = 0; j < 4; j++) {
        int g = j * 256 + h;
        dst[j]     = wi[g];
        dst[4 + j] = bi[g] + bh[g];
    }
}

// ---------------- math helpers ----------------

__device__ __forceinline__ float sigm_(float x) {
    // exp overflow/underflow saturates correctly (inf -> 0, 0 -> 1); no NaN path.
    return __fdividef(1.0f, 1.0f + __expf(-x));
}
__device__ __forceinline__ float tanh_(float x) {
    float xc = fminf(9.0f, fmaxf(-9.0f, x));
    float e = __expf(2.0f * xc);
    return __fdividef(e - 1.0f, e + 1.0f);
}
__device__ __forceinline__ unsigned long long pack2(float a) {
    unsigned long long r;
    unsigned int u = __float_as_uint(a);
    asm("mov.b64 %0, {%1, %1};" : "=l"(r) : "r"(u));
    return r;
}

// ---------------- main kernel ----------------

__global__ void __launch_bounds__(256, 1)
lstm_main(const float* __restrict__ x, const float* __restrict__ w_s,
          const float* __restrict__ b_s, const float* __restrict__ gamma,
          const float* __restrict__ beta, float* __restrict__ out) {
    __shared__ float sx[TB][28];
    __shared__ float hT[256][18];   // [k][row], +2 pad; row pairs 8B-aligned (18*4=72)
    __shared__ float smu[TB];
    __shared__ float srs[TB];

    const int tid  = threadIdx.x;
    const int row0 = blockIdx.x * TB;

    // load x slice for this CTA
    for (int i = tid; i < TB * 28; i += 256) {
        int r = i / 28, c = i % 28;
        sx[r][c] = x[(row0 + r) * 28 + c];
    }
    __syncthreads();

    // scalar embedding init: emb[r] = b_s[h] + sum_j x[r][j]*w_s[h][j], h = tid
    float emb[TB];
    {
        float4 wsv = *reinterpret_cast<const float4*>(w_s + tid * 4);
        float bsv = b_s[tid];
#pragma unroll
        for (int r = 0; r < TB; r++) {
            float v = bsv;
            v = fmaf(sx[r][0], wsv.x, v);
            v = fmaf(sx[r][1], wsv.y, v);
            v = fmaf(sx[r][2], wsv.z, v);
            v = fmaf(sx[r][3], wsv.w, v);
            emb[r] = v;
        }
    }

    for (int l = 0; l < 4; l++) {
        float c_[TB];
#pragma unroll
        for (int r = 0; r < TB; r++) c_[r] = 0.0f;
#pragma unroll
        for (int r = 0; r < TB; r++) hT[tid][r] = 0.0f;   // thread owns k=tid slice

        const float4 wi = *reinterpret_cast<const float4*>(g_wb + (l * 256 + tid) * 8);
        const float4 bi = *reinterpret_cast<const float4*>(g_wb + (l * 256 + tid) * 8 + 4);
        const int T = (l < 2) ? 9 : 15;
        const float4* Wl = reinterpret_cast<const float4*>(g_W2) + l * 65536 + tid;

        __syncthreads();   // hT zeros visible

        for (int t = 0; t < T; t++) {
            // ---- gate matvec: acc[j][row] = sum_k whh[j*256+tid][k] * h[row][k] ----
            unsigned long long acc2[4][8];
#pragma unroll
            for (int j = 0; j < 4; j++)
#pragma unroll
                for (int p = 0; p < 8; p++) acc2[j][p] = 0ull;

#pragma unroll 4
            for (int k = 0; k < 256; k++) {
                float4 w4 = Wl[k * 256];                 // coalesced LDG.128
                unsigned long long w2[4];
                w2[0] = pack2(w4.x);
                w2[1] = pack2(w4.y);
                w2[2] = pack2(w4.z);
                w2[3] = pack2(w4.w);
                const unsigned long long* hp =
                    reinterpret_cast<const unsigned long long*>(&hT[k][0]);
                unsigned long long h2[8];
#pragma unroll
                for (int p = 0; p < 8; p++) h2[p] = hp[p];   // broadcast LDS.64
#pragma unroll
                for (int j = 0; j < 4; j++)
#pragma unroll
                    for (int p = 0; p < 8; p++)
                        asm("fma.rn.f32x2 %0, %1, %2, %0;"
                            : "+l"(acc2[j][p]) : "l"(h2[p]), "l"(w2[j]));
            }
            __syncthreads();   // all reads of hT complete before rewrite

            // seq column for this (lstm, t)
            int col;
            if (l == 0)      col = 4 + t;
            else if (l == 1) col = 12 - t;
            else if (l == 2) col = 13 + t;
            else             col = 27 - t;

            const bool last = (t == T - 1);
#pragma unroll
            for (int p = 0; p < 8; p++) {
                float a[8];
#pragma unroll
                for (int j = 0; j < 4; j++) {
                    unsigned int lo, hi;
                    asm("mov.b64 {%0, %1}, %2;" : "=r"(lo), "=r"(hi) : "l"(acc2[j][p]));
                    a[j]     = __uint_as_float(lo);   // row 2p
                    a[4 + j] = __uint_as_float(hi);   // row 2p+1
                }
#pragma unroll
                for (int half = 0; half < 2; half++) {
                    int r = 2 * p + half;
                    float sv = sx[r][col];
                    float gi = fmaf(sv, wi.x, bi.x) + a[half * 4 + 0];
                    float gf = fmaf(sv, wi.y, bi.y) + a[half * 4 + 1];
                    float gg = fmaf(sv, wi.z, bi.z) + a[half * 4 + 2];
                    float go = fmaf(sv, wi.w, bi.w) + a[half * 4 + 3];
                    float si = sigm_(gi), sf = sigm_(gf);
                    float tg = tanh_(gg), so = sigm_(go);
                    c_[r] = sf * c_[r] + si * tg;
                    float hn = so * tanh_(c_[r]);
                    hT[tid][r] = hn;
                    if (last) emb[r] += hn;
                }
            }
            __syncthreads();   // new hT visible before next step
        }
    }

    // ---- layernorm over hidden dim, per row ----
    float* gbuf = &hT[0][0];   // reuse hT storage (4608 floats >= 16*256)
#pragma unroll
    for (int r = 0; r < TB; r++) gbuf[r * 256 + tid] = emb[r];
    __syncthreads();

    int wid = tid >> 5, lane = tid & 31;
#pragma unroll
    for (int rr = wid * 2; rr < wid * 2 + 2; rr++) {
        float s = 0.0f, sq = 0.0f;
#pragma unroll
        for (int i = 0; i < 8; i++) {
            float v = gbuf[rr * 256 + lane + 32 * i];
            s += v;
            sq = fmaf(v, v, sq);
        }
#pragma unroll
        for (int o = 16; o > 0; o >>= 1) {
            s  += __shfl_xor_sync(0xFFFFFFFFu, s, o);
            sq += __shfl_xor_sync(0xFFFFFFFFu, sq, o);
        }
        if (lane == 0) {
            float mu = s * (1.0f / 256.0f);
            float var = sq * (1.0f / 256.0f) - mu * mu;
            smu[rr] = mu;
            srs[rr] = rsqrtf(var + LN_EPS);
        }
    }
    __syncthreads();

    float ga = gamma[tid], be = beta[tid];
#pragma unroll
    for (int r = 0; r < TB; r++) {
        out[(row0 + r) * 256 + tid] = (emb[r] - smu[r]) * srs[r] * ga + be;
    }
}

// ---------------- launch ----------------

extern "C" void kernel_launch(void* const* d_in, const int* in_sizes, int n_in,
                              void* d_out, int out_size) {
    (void)in_sizes; (void)n_in; (void)out_size;
    const float* x     = (const float*)d_in[0];
    const float* w_s   = (const float*)d_in[1];
    const float* b_s   = (const float*)d_in[2];
    // per-LSTM params: base 3 + 4*l : wih, whh, bih, bhh
    const float* wih[4], *whh[4], *bih[4], *bhh[4];
    for (int l = 0; l < 4; l++) {
        wih[l] = (const float*)d_in[3 + 4 * l + 0];
        whh[l] = (const float*)d_in[3 + 4 * l + 1];
        bih[l] = (const float*)d_in[3 + 4 * l + 2];
        bhh[l] = (const float*)d_in[3 + 4 * l + 3];
    }
    const float* gamma = (const float*)d_in[19];
    const float* beta  = (const float*)d_in[20];
    float* out = (float*)d_out;

    prep_w2<<<1024, 256>>>(whh[0], whh[1], whh[2], whh[3]);
    prep_wb<<<4, 256>>>(wih[0], bih[0], bhh[0],
                        wih[1], bih[1], bhh[1],
                        wih[2], bih[2], bhh[2],
                        wih[3], bih[3], bhh[3]);
    lstm_main<<<NBATCH / TB, 256>>>(x, w_s, b_s, gamma, beta, out);
}